// round 14
// baseline (speedup 1.0000x reference)
#include <cuda_runtime.h>
#include <cuda_fp16.h>
#include <cstdint>

// Problem constants (fixed by the reference)
#define NN 50000
#define EE 800000
#define IN_C 512
#define HID_C 128
#define OUT_C 256
#define NB 196          // ceil(NN / 256)

// Scratch (allocation-free rule: __device__ globals)
__device__ __align__(16) __half g_h1[(size_t)NN * HID_C];    // x @ w1^T   (fp16)
__device__ __align__(16) __half g_agg1[(size_t)NN * HID_C];  // relu(A*h1 + b1) (fp16)
__device__ __align__(16) __half g_agg2[(size_t)NN * HID_C];  // A*relu(agg1) (fp16)
__device__ int g_count[NN];
__device__ int g_rowptr[NN + 1];
__device__ int g_cursor[NN];
__device__ int g_blksum[NB];
__device__ int g_csr_src[EE];

__device__ __forceinline__ uint32_t f2tf32(float f) {
    uint32_t r;
    asm("cvt.rna.tf32.f32 %0, %1;" : "=r"(r) : "f"(f));
    return r;
}
__device__ __forceinline__ uint32_t pack_f16x2(float lo, float hi) {
    uint32_t r;
    asm("cvt.rn.f16x2.f32 %0, %1, %2;" : "=r"(r) : "f"(hi), "f"(lo));
    return r;
}

// ---------------------------------------------------------------------------
// TF32 tensor-core GEMM (fp32 A) with 2-stage cp.async pipeline. (GEMM1)
// ---------------------------------------------------------------------------
template <int K, int NTOT, bool BIAS, bool HALF_OUT>
__global__ __launch_bounds__(256)
void gemm_tf32(const float* __restrict__ A, const float* __restrict__ W,
               const float* __restrict__ bias, void* __restrict__ Cv, int M) {
    constexpr int BM = 128, BN = 64, BK = 32, LDS = BK + 4;
    constexpr int TILES = K / BK;
    __shared__ float As[2][BM][LDS];
    __shared__ float Bs[2][BN][LDS];

    const int tid = threadIdx.x;
    const int lane = tid & 31;
    const int wid = tid >> 5;
    const int warp_m = wid >> 1;
    const int warp_n = wid & 1;
    const int bm = blockIdx.y * BM;
    const int bn = blockIdx.x * BN;
    const int a_row = tid >> 3;
    const int a_c4 = (tid & 7) * 4;

    float acc[2][4][4];
#pragma unroll
    for (int mf = 0; mf < 2; mf++)
#pragma unroll
        for (int nf = 0; nf < 4; nf++)
#pragma unroll
            for (int r = 0; r < 4; r++) acc[mf][nf][r] = 0.0f;

    auto load_stage = [&](int stage, int k0) {
#pragma unroll
        for (int i = 0; i < 4; i++) {
            int row = a_row + i * 32;
            const float* gp = A + (size_t)(bm + row) * K + k0 + a_c4;
            uint32_t sa = (uint32_t)__cvta_generic_to_shared(&As[stage][row][a_c4]);
            int sz = (bm + row < M) ? 16 : 0;
            asm volatile("cp.async.cg.shared.global [%0], [%1], 16, %2;"
                         :: "r"(sa), "l"(gp), "r"(sz));
        }
#pragma unroll
        for (int i = 0; i < 2; i++) {
            int row = a_row + i * 32;
            const float* gp = W + (size_t)(bn + row) * K + k0 + a_c4;
            uint32_t sa = (uint32_t)__cvta_generic_to_shared(&Bs[stage][row][a_c4]);
            asm volatile("cp.async.cg.shared.global [%0], [%1], 16;"
                         :: "r"(sa), "l"(gp));
        }
        asm volatile("cp.async.commit_group;");
    };

    load_stage(0, 0);

    for (int t = 0; t < TILES; t++) {
        const int buf = t & 1;
        if (t + 1 < TILES) {
            load_stage(buf ^ 1, (t + 1) * BK);
            asm volatile("cp.async.wait_group 1;");
        } else {
            asm volatile("cp.async.wait_group 0;");
        }
        __syncthreads();

#pragma unroll
        for (int ks = 0; ks < BK / 8; ks++) {
            const int kb = ks * 8;
            const int kc = kb + (lane & 3);
            uint32_t a[2][4], b[4][2];
#pragma unroll
            for (int mf = 0; mf < 2; mf++) {
                int mr = warp_m * 32 + mf * 16 + (lane >> 2);
                a[mf][0] = f2tf32(As[buf][mr][kc]);
                a[mf][1] = f2tf32(As[buf][mr + 8][kc]);
                a[mf][2] = f2tf32(As[buf][mr][kc + 4]);
                a[mf][3] = f2tf32(As[buf][mr + 8][kc + 4]);
            }
#pragma unroll
            for (int nf = 0; nf < 4; nf++) {
                int nr = warp_n * 32 + nf * 8 + (lane >> 2);
                b[nf][0] = f2tf32(Bs[buf][nr][kc]);
                b[nf][1] = f2tf32(Bs[buf][nr][kc + 4]);
            }
#pragma unroll
            for (int mf = 0; mf < 2; mf++)
#pragma unroll
                for (int nf = 0; nf < 4; nf++) {
                    asm volatile(
                        "mma.sync.aligned.m16n8k8.row.col.f32.tf32.tf32.f32 "
                        "{%0,%1,%2,%3}, {%4,%5,%6,%7}, {%8,%9}, {%0,%1,%2,%3};\n"
                        : "+f"(acc[mf][nf][0]), "+f"(acc[mf][nf][1]),
                          "+f"(acc[mf][nf][2]), "+f"(acc[mf][nf][3])
                        : "r"(a[mf][0]), "r"(a[mf][1]), "r"(a[mf][2]), "r"(a[mf][3]),
                          "r"(b[nf][0]), "r"(b[nf][1]));
                }
        }
        __syncthreads();
    }

#pragma unroll
    for (int mf = 0; mf < 2; mf++) {
#pragma unroll
        for (int nf = 0; nf < 4; nf++) {
            int gr = bm + warp_m * 32 + mf * 16 + (lane >> 2);
            int gc = bn + warp_n * 32 + nf * 8 + 2 * (lane & 3);
            float b0 = 0.f, b1 = 0.f;
            if (BIAS) { b0 = __ldg(bias + gc); b1 = __ldg(bias + gc + 1); }
            if (HALF_OUT) {
                __half* C = (__half*)Cv;
                if (gr < M)
                    *reinterpret_cast<__half2*>(C + (size_t)gr * NTOT + gc) =
                        __floats2half2_rn(acc[mf][nf][0] + b0, acc[mf][nf][1] + b1);
                if (gr + 8 < M)
                    *reinterpret_cast<__half2*>(C + (size_t)(gr + 8) * NTOT + gc) =
                        __floats2half2_rn(acc[mf][nf][2] + b0, acc[mf][nf][3] + b1);
            } else {
                float* C = (float*)Cv;
                if (gr < M)
                    *reinterpret_cast<float2*>(C + (size_t)gr * NTOT + gc) =
                        make_float2(acc[mf][nf][0] + b0, acc[mf][nf][1] + b1);
                if (gr + 8 < M)
                    *reinterpret_cast<float2*>(C + (size_t)(gr + 8) * NTOT + gc) =
                        make_float2(acc[mf][nf][2] + b0, acc[mf][nf][3] + b1);
            }
        }
    }
}

// ---------------------------------------------------------------------------
// fp16-A tensor-core GEMM (GEMM2): A is __half [M,K]; W fp32 [N,K]; C fp32.
// ---------------------------------------------------------------------------
template <int K, int NTOT, bool BIAS>
__global__ __launch_bounds__(256)
void gemm_f16a(const __half* __restrict__ A, const float* __restrict__ W,
               const float* __restrict__ bias, float* __restrict__ C, int M) {
    constexpr int BM = 128, BN = 64, BK = 32;
    constexpr int LDH = BK + 16;
    constexpr int LDS = BK + 4;
    constexpr int TILES = K / BK;
    __shared__ __half Ah[2][BM][LDH];
    __shared__ float Bs[2][BN][LDS];

    const int tid = threadIdx.x;
    const int lane = tid & 31;
    const int wid = tid >> 5;
    const int warp_m = wid >> 1;
    const int warp_n = wid & 1;
    const int bm = blockIdx.y * BM;
    const int bn = blockIdx.x * BN;

    float acc[2][4][4];
#pragma unroll
    for (int mf = 0; mf < 2; mf++)
#pragma unroll
        for (int nf = 0; nf < 4; nf++)
#pragma unroll
            for (int r = 0; r < 4; r++) acc[mf][nf][r] = 0.0f;

    auto load_stage = [&](int stage, int k0) {
#pragma unroll
        for (int i = 0; i < 2; i++) {
            int idx = tid + i * 256;
            int row = idx >> 2;
            int ch = (idx & 3) * 8;
            const __half* gp = A + (size_t)(bm + row) * K + k0 + ch;
            uint32_t sa = (uint32_t)__cvta_generic_to_shared(&Ah[stage][row][ch]);
            int sz = (bm + row < M) ? 16 : 0;
            asm volatile("cp.async.cg.shared.global [%0], [%1], 16, %2;"
                         :: "r"(sa), "l"(gp), "r"(sz));
        }
#pragma unroll
        for (int i = 0; i < 2; i++) {
            int idx = tid + i * 256;
            int row = idx >> 3;
            int c4 = (idx & 7) * 4;
            const float* gp = W + (size_t)(bn + row) * K + k0 + c4;
            uint32_t sa = (uint32_t)__cvta_generic_to_shared(&Bs[stage][row][c4]);
            asm volatile("cp.async.cg.shared.global [%0], [%1], 16;"
                         :: "r"(sa), "l"(gp));
        }
        asm volatile("cp.async.commit_group;");
    };

    load_stage(0, 0);

    for (int t = 0; t < TILES; t++) {
        const int buf = t & 1;
        if (t + 1 < TILES) {
            load_stage(buf ^ 1, (t + 1) * BK);
            asm volatile("cp.async.wait_group 1;");
        } else {
            asm volatile("cp.async.wait_group 0;");
        }
        __syncthreads();

#pragma unroll
        for (int ks = 0; ks < BK / 16; ks++) {
            const int kb = ks * 16;
            const int kp = kb + 2 * (lane & 3);
            uint32_t a[2][4], b[4][2];
#pragma unroll
            for (int mf = 0; mf < 2; mf++) {
                int mr = warp_m * 32 + mf * 16 + (lane >> 2);
                a[mf][0] = *reinterpret_cast<const uint32_t*>(&Ah[buf][mr][kp]);
                a[mf][1] = *reinterpret_cast<const uint32_t*>(&Ah[buf][mr + 8][kp]);
                a[mf][2] = *reinterpret_cast<const uint32_t*>(&Ah[buf][mr][kp + 8]);
                a[mf][3] = *reinterpret_cast<const uint32_t*>(&Ah[buf][mr + 8][kp + 8]);
            }
#pragma unroll
            for (int nf = 0; nf < 4; nf++) {
                int nr = warp_n * 32 + nf * 8 + (lane >> 2);
                float2 f0 = *reinterpret_cast<const float2*>(&Bs[buf][nr][kp]);
                float2 f1 = *reinterpret_cast<const float2*>(&Bs[buf][nr][kp + 8]);
                b[nf][0] = pack_f16x2(f0.x, f0.y);
                b[nf][1] = pack_f16x2(f1.x, f1.y);
            }
#pragma unroll
            for (int mf = 0; mf < 2; mf++)
#pragma unroll
                for (int nf = 0; nf < 4; nf++) {
                    asm volatile(
                        "mma.sync.aligned.m16n8k16.row.col.f32.f16.f16.f32 "
                        "{%0,%1,%2,%3}, {%4,%5,%6,%7}, {%8,%9}, {%0,%1,%2,%3};\n"
                        : "+f"(acc[mf][nf][0]), "+f"(acc[mf][nf][1]),
                          "+f"(acc[mf][nf][2]), "+f"(acc[mf][nf][3])
                        : "r"(a[mf][0]), "r"(a[mf][1]), "r"(a[mf][2]), "r"(a[mf][3]),
                          "r"(b[nf][0]), "r"(b[nf][1]));
                }
        }
        __syncthreads();
    }

#pragma unroll
    for (int mf = 0; mf < 2; mf++) {
#pragma unroll
        for (int nf = 0; nf < 4; nf++) {
            int gr = bm + warp_m * 32 + mf * 16 + (lane >> 2);
            int gc = bn + warp_n * 32 + nf * 8 + 2 * (lane & 3);
            float b0 = 0.f, b1 = 0.f;
            if (BIAS) { b0 = __ldg(bias + gc); b1 = __ldg(bias + gc + 1); }
            if (gr < M)
                *reinterpret_cast<float2*>(C + (size_t)gr * NTOT + gc) =
                    make_float2(acc[mf][nf][0] + b0, acc[mf][nf][1] + b1);
            if (gr + 8 < M)
                *reinterpret_cast<float2*>(C + (size_t)(gr + 8) * NTOT + gc) =
                    make_float2(acc[mf][nf][2] + b0, acc[mf][nf][3] + b1);
        }
    }
}

// ---------------------------------------------------------------------------
// CSR construction: histogram -> block sums -> rowptr(fused scan) -> fill
// hist/fill are 4-wide batched for MLP (atomic chains were issue=5%).
// ---------------------------------------------------------------------------
__global__ void hist_dst(const int* __restrict__ dst, int* __restrict__ count, int E) {
    int base = (blockIdx.x * blockDim.x + threadIdx.x) * 4;
    int stride = gridDim.x * blockDim.x * 4;
    for (; base < E; base += stride) {
        int d[4];
        int n = (E - base >= 4) ? 4 : (E - base);
#pragma unroll
        for (int j = 0; j < 4; j++) d[j] = (j < n) ? __ldg(dst + base + j) : -1;
#pragma unroll
        for (int j = 0; j < 4; j++)
            if ((unsigned)d[j] < NN) atomicAdd(count + d[j], 1);
    }
}

__global__ __launch_bounds__(256)
void block_sums(const int* __restrict__ count, int* __restrict__ bsum) {
    __shared__ int sh[256];
    int i = blockIdx.x * 256 + threadIdx.x;
    sh[threadIdx.x] = (i < NN) ? count[i] : 0;
    __syncthreads();
    for (int off = 128; off > 0; off >>= 1) {
        if (threadIdx.x < off) sh[threadIdx.x] += sh[threadIdx.x + off];
        __syncthreads();
    }
    if (threadIdx.x == 0) bsum[blockIdx.x] = sh[0];
}

__global__ __launch_bounds__(256)
void write_rowptr(const int* __restrict__ count, const int* __restrict__ bsum,
                  int* __restrict__ rowptr, int* __restrict__ cursor) {
    __shared__ int sb[256];
    __shared__ int sh[256];
    int t = threadIdx.x;
    int bb = blockIdx.x;

    int bv = (t < NB) ? __ldg(bsum + t) : 0;
    sb[t] = bv;
    int i = bb * 256 + t;
    int v = (i < NN) ? count[i] : 0;
    sh[t] = v;
    __syncthreads();
    for (int off = 1; off < 256; off <<= 1) {
        int addb = (t >= off) ? sb[t - off] : 0;
        int addv = (t >= off) ? sh[t - off] : 0;
        __syncthreads();
        sb[t] += addb;
        sh[t] += addv;
        __syncthreads();
    }
    int boff = sb[bb] - __ldg(bsum + bb);
    if (i < NN) {
        int rp = boff + sh[t] - v;
        rowptr[i] = rp;
        cursor[i] = rp;
    }
    if (bb == 0 && t == NB - 1) rowptr[NN] = sb[NB - 1];
}

__global__ void fill_csr(const int* __restrict__ ei, int* __restrict__ cursor,
                         int* __restrict__ csr_src, int E) {
    const int* __restrict__ src = ei;
    const int* __restrict__ dst = ei + E;
    int base = (blockIdx.x * blockDim.x + threadIdx.x) * 4;
    int stride = gridDim.x * blockDim.x * 4;
    for (; base < E; base += stride) {
        int n = (E - base >= 4) ? 4 : (E - base);
        int d[4], s[4];
#pragma unroll
        for (int j = 0; j < 4; j++) {
            d[j] = (j < n) ? __ldg(dst + base + j) : -1;
            s[j] = (j < n) ? __ldg(src + base + j) : 0;
        }
        int pos[4];
#pragma unroll
        for (int j = 0; j < 4; j++)
            pos[j] = ((unsigned)d[j] < NN) ? atomicAdd(cursor + d[j], 1) : -1;
#pragma unroll
        for (int j = 0; j < 4; j++)
            if (pos[j] >= 0) csr_src[pos[j]] = s[j];
    }
}

// ---------------------------------------------------------------------------
// fp16 gather aggregation (warp per node). Rows are 128 halves = 32 uint2.
// 8-wide unrolled body; fp32 accumulation. RELU_OUT applies relu before store.
// ---------------------------------------------------------------------------
__device__ __forceinline__ void acc_u2(float4& acc, uint2 u) {
    float2 fa = __half22float2(*reinterpret_cast<__half2*>(&u.x));
    float2 fb = __half22float2(*reinterpret_cast<__half2*>(&u.y));
    acc.x += fa.x; acc.y += fa.y; acc.z += fb.x; acc.w += fb.y;
}

template <bool BIAS, bool RELU_OUT>
__global__ __launch_bounds__(256)
void agg_gather_h16(const uint2* __restrict__ H, const int* __restrict__ rowptr,
                    const int* __restrict__ csr_src, const float* __restrict__ bias,
                    uint2* __restrict__ OUT) {
    const int warp = (blockIdx.x * blockDim.x + threadIdx.x) >> 5;
    const int lane = threadIdx.x & 31;
    if (warp >= NN) return;

    const int start = __ldg(rowptr + warp);
    const int end = __ldg(rowptr + warp + 1);

    float4 acc = BIAS ? __ldg(reinterpret_cast<const float4*>(bias) + lane)
                      : make_float4(0.f, 0.f, 0.f, 0.f);

    int i = start;
    for (; i + 8 <= end; i += 8) {
        int s[8];
#pragma unroll
        for (int j = 0; j < 8; j++) s[j] = __ldg(csr_src + i + j);
        uint2 u[8];
#pragma unroll
        for (int j = 0; j < 8; j++) u[j] = __ldg(H + (size_t)s[j] * 32 + lane);
#pragma unroll
        for (int j = 0; j < 8; j++) acc_u2(acc, u[j]);
    }
    for (; i + 4 <= end; i += 4) {
        int s0 = __ldg(csr_src + i);
        int s1 = __ldg(csr_src + i + 1);
        int s2 = __ldg(csr_src + i + 2);
        int s3 = __ldg(csr_src + i + 3);
        uint2 u0 = __ldg(H + (size_t)s0 * 32 + lane);
        uint2 u1 = __ldg(H + (size_t)s1 * 32 + lane);
        uint2 u2 = __ldg(H + (size_t)s2 * 32 + lane);
        uint2 u3 = __ldg(H + (size_t)s3 * 32 + lane);
        acc_u2(acc, u0);
        acc_u2(acc, u1);
        acc_u2(acc, u2);
        acc_u2(acc, u3);
    }
    for (; i < end; i++) {
        int s = __ldg(csr_src + i);
        acc_u2(acc, __ldg(H + (size_t)s * 32 + lane));
    }

    if (RELU_OUT) {
        acc.x = fmaxf(acc.x, 0.f); acc.y = fmaxf(acc.y, 0.f);
        acc.z = fmaxf(acc.z, 0.f); acc.w = fmaxf(acc.w, 0.f);
    }
    __half2 h0 = __floats2half2_rn(acc.x, acc.y);
    __half2 h1 = __floats2half2_rn(acc.z, acc.w);
    uint2 o;
    o.x = *reinterpret_cast<uint32_t*>(&h0);
    o.y = *reinterpret_cast<uint32_t*>(&h1);
    OUT[(size_t)warp * 32 + lane] = o;
}

extern "C" void kernel_launch(void* const* d_in, const int* in_sizes, int n_in,
                              void* d_out, int out_size) {
    const float* x = (const float*)d_in[0];
    const int* edge_index = (const int*)d_in[1];
    const float* w1 = (const float*)d_in[2];
    const float* b1 = (const float*)d_in[3];
    const float* w2 = (const float*)d_in[4];
    const float* b2 = (const float*)d_in[5];
    float* out = (float*)d_out;

    __half* h1;   cudaGetSymbolAddress((void**)&h1, g_h1);
    __half* agg1; cudaGetSymbolAddress((void**)&agg1, g_agg1);
    __half* agg2; cudaGetSymbolAddress((void**)&agg2, g_agg2);
    int* count;   cudaGetSymbolAddress((void**)&count, g_count);
    int* rowptr;  cudaGetSymbolAddress((void**)&rowptr, g_rowptr);
    int* cursor;  cudaGetSymbolAddress((void**)&cursor, g_cursor);
    int* bsum;    cudaGetSymbolAddress((void**)&bsum, g_blksum);
    int* csr_src; cudaGetSymbolAddress((void**)&csr_src, g_csr_src);

    static cudaStream_t s2 = nullptr;
    static cudaEvent_t ev_fork = nullptr, ev_join = nullptr;
    if (s2 == nullptr) {
        cudaStreamCreateWithFlags(&s2, cudaStreamNonBlocking);
        cudaEventCreateWithFlags(&ev_fork, cudaEventDisableTiming);
        cudaEventCreateWithFlags(&ev_join, cudaEventDisableTiming);
    }

    // ---- Fork: CSR build on s2 (issued first so ncu -s5 lands on main chain) ----
    cudaEventRecord(ev_fork, 0);
    cudaStreamWaitEvent(s2, ev_fork, 0);

    cudaMemsetAsync(count, 0, NN * sizeof(int), s2);
    hist_dst<<<800, 256, 0, s2>>>(edge_index + EE, count, EE);
    block_sums<<<NB, 256, 0, s2>>>(count, bsum);
    write_rowptr<<<NB, 256, 0, s2>>>(count, bsum, rowptr, cursor);
    fill_csr<<<800, 256, 0, s2>>>(edge_index, cursor, csr_src, EE);
    cudaEventRecord(ev_join, s2);

    // ---- h1 = x @ w1^T  -> fp16   (main stream, overlaps CSR build) ----
    {
        dim3 grid(HID_C / 64, (NN + 127) / 128);
        gemm_tf32<IN_C, HID_C, false, true><<<grid, 256>>>(x, w1, nullptr, h1, NN);
    }

    // ---- Join: gathers need both h1 and the CSR ----
    cudaStreamWaitEvent(0, ev_join, 0);

    // ---- agg1[n] = fp16(relu(b1 + sum h1[src in(n)]))  (relu folded) ----
    agg_gather_h16<true, true><<<(NN * 32 + 255) / 256, 256>>>(
        (const uint2*)h1, rowptr, csr_src, b1, (uint2*)agg1);
    // ---- agg2[n] = fp16 sum agg1[src in(n)]  (inputs pre-relu'd) ----
    agg_gather_h16<false, false><<<(NN * 32 + 255) / 256, 256>>>(
        (const uint2*)agg1, rowptr, csr_src, nullptr, (uint2*)agg2);
    // ---- out = agg2 @ w2^T + b2   (fp16-A mma) ----
    {
        dim3 grid(OUT_C / 64, (NN + 127) / 128);
        gemm_f16a<HID_C, OUT_C, true><<<grid, 256>>>(agg2, w2, b2, out, NN);
    }
}